// round 5
// baseline (speedup 1.0000x reference)
#include <cuda_runtime.h>

// SpectralAttention: B=1024, S=3, A=256, D=256
// HBM-bound streaming reduction (1.07 GB reads). R5 = R2 read path with the
// four long-lived weight float4s moved to shared memory (2KB, conflict-free
// lane-striped LDS), freeing ~16 regs so __launch_bounds__(256,5) fits 5
// CTAs/SM: 40 warps x 8 front-batched LDG.128 = 320 in-flight loads/SM
// (vs 256 in R2), pushing DRAM utilization toward the ceiling.

#define BB 1024
#define SS 3
#define AA 256
#define DD 256

__global__ __launch_bounds__(256, 5)
void spectral_attention_kernel(const float* __restrict__ input,
                               const float* __restrict__ scattered,
                               const float* __restrict__ weight,
                               const float* __restrict__ prelu,
                               float* __restrict__ out)
{
    __shared__ float4 wsh[128];   // 512 floats = 2KB: w1 = [0..63], w2 = [64..127]

    const int tid  = threadIdx.x;
    const int lane = tid & 31;

    // Stage weights into smem (threads 0..127 each copy one float4).
    if (tid < 128) {
        wsh[tid] = __ldg(&reinterpret_cast<const float4*>(weight)[tid]);
    }

    const int warp = (blockIdx.x * blockDim.x + tid) >> 5;  // 0 .. B*A-1
    const int b = warp >> 8;    // / AA
    const int a = warp & 255;   // % AA

    // ---- Front-batch ALL stream loads (8x LDG.128, evict-first) ----
    const float4* __restrict__ xr =
        reinterpret_cast<const float4*>(input + (((size_t)b * AA + a) * DD));
    const float4* __restrict__ y0r = reinterpret_cast<const float4*>(
        scattered + ((((size_t)b * SS + 0) * AA + a) * (size_t)DD));
    const float4* __restrict__ y1r = reinterpret_cast<const float4*>(
        scattered + ((((size_t)b * SS + 1) * AA + a) * (size_t)DD));
    const float4* __restrict__ y2r = reinterpret_cast<const float4*>(
        scattered + ((((size_t)b * SS + 2) * AA + a) * (size_t)DD));

    const float4 x0  = __ldcs(&xr[lane]);
    const float4 x1  = __ldcs(&xr[lane + 32]);
    const float4 ya0 = __ldcs(&y0r[lane]);
    const float4 ya1 = __ldcs(&y0r[lane + 32]);
    const float4 yb0 = __ldcs(&y1r[lane]);
    const float4 yb1 = __ldcs(&y1r[lane + 32]);
    const float4 yc0 = __ldcs(&y2r[lane]);
    const float4 yc1 = __ldcs(&y2r[lane + 32]);

    __syncthreads();   // weights visible (overlapped with in-flight LDGs)

    // ---- Weights from smem: short-lived registers, loaded just-in-time ----
    const float4 w1a = wsh[lane];
    const float4 w1b = wsh[lane + 32];
    float p_in = x0.x * w1a.x + x0.y * w1a.y + x0.z * w1a.z + x0.w * w1a.w
               + x1.x * w1b.x + x1.y * w1b.y + x1.z * w1b.z + x1.w * w1b.w;

    const float4 w2a = wsh[64 + lane];
    const float4 w2b = wsh[64 + lane + 32];
    float p0 = ya0.x * w2a.x + ya0.y * w2a.y + ya0.z * w2a.z + ya0.w * w2a.w
             + ya1.x * w2b.x + ya1.y * w2b.y + ya1.z * w2b.z + ya1.w * w2b.w;
    float p1 = yb0.x * w2a.x + yb0.y * w2a.y + yb0.z * w2a.z + yb0.w * w2a.w
             + yb1.x * w2b.x + yb1.y * w2b.y + yb1.z * w2b.z + yb1.w * w2b.w;
    float p2 = yc0.x * w2a.x + yc0.y * w2a.y + yc0.z * w2a.z + yc0.w * w2a.w
             + yc1.x * w2b.x + yc1.y * w2b.y + yc1.z * w2b.z + yc1.w * w2b.w;

    // Butterfly reduce all 4 partial dots.
#pragma unroll
    for (int off = 16; off > 0; off >>= 1) {
        p_in += __shfl_xor_sync(0xffffffffu, p_in, off);
        p0   += __shfl_xor_sync(0xffffffffu, p0, off);
        p1   += __shfl_xor_sync(0xffffffffu, p1, off);
        p2   += __shfl_xor_sync(0xffffffffu, p2, off);
    }

    const float alpha = __ldg(prelu);
    float sc0 = p_in + p0;
    float sc1 = p_in + p1;
    float sc2 = p_in + p2;
    sc0 = sc0 >= 0.f ? sc0 : alpha * sc0;
    sc1 = sc1 >= 0.f ? sc1 : alpha * sc1;
    sc2 = sc2 >= 0.f ? sc2 : alpha * sc2;

    const float m = fmaxf(sc0, fmaxf(sc1, sc2));
    const float e0 = __expf(sc0 - m);
    const float e1 = __expf(sc1 - m);
    const float e2 = __expf(sc2 - m);
    const float inv = 1.0f / (e0 + e1 + e2);

    if (lane < SS) {
        const float e = (lane == 0) ? e0 : (lane == 1 ? e1 : e2);
        out[((size_t)b * SS + lane) * AA + a] = e * inv;
    }
}

extern "C" void kernel_launch(void* const* d_in, const int* in_sizes, int n_in,
                              void* d_out, int out_size)
{
    const float* input     = (const float*)d_in[0];  // (B, A, D) f32
    const float* scattered = (const float*)d_in[1];  // (B, S, A, D) f32
    const float* weight    = (const float*)d_in[2];  // (2D,) f32
    const float* prelu     = (const float*)d_in[3];  // (1,) f32
    float* out = (float*)d_out;                      // (B, S, A) f32

    const int total_warps = BB * AA;                 // 262144
    const int threads = 256;                         // 8 warps / block
    const int blocks = total_warps / (threads / 32); // 32768
    spectral_attention_kernel<<<blocks, threads>>>(input, scattered, weight, prelu, out);
}

// round 6
// speedup vs baseline: 1.0072x; 1.0072x over previous
#include <cuda_runtime.h>

// SpectralAttention: B=1024, S=3, A=256, D=256
// HBM-bound streaming reduction: 1.07 GB mandatory reads, measured chip
// streaming ceiling ~7.2 TB/s (LTS cap, path-independent) -> ~149us floor.
// R6 = R2 config (empirically optimal: 4 CTAs/SM, 8 front-batched LDG.128
// per warp, __ldcs evict-first) + __stcs streaming output stores.
// R3 (persistent+pipeline), R4 (smem-staged writes), R5 (5 CTAs/SM via smem
// weights) all measured worse; occupancy/MLP optimum is this configuration.

#define BB 1024
#define SS 3
#define AA 256
#define DD 256

__global__ __launch_bounds__(256, 4)
void spectral_attention_kernel(const float* __restrict__ input,
                               const float* __restrict__ scattered,
                               const float* __restrict__ weight,
                               const float* __restrict__ prelu,
                               float* __restrict__ out)
{
    const int lane = threadIdx.x & 31;
    const int warp = (blockIdx.x * blockDim.x + threadIdx.x) >> 5;  // 0 .. B*A-1
    const int b = warp >> 8;    // / AA
    const int a = warp & 255;   // % AA

    // ---- Front-batch ALL stream loads (8x LDG.128, evict-first) ----
    const float4* __restrict__ xr =
        reinterpret_cast<const float4*>(input + (((size_t)b * AA + a) * DD));
    const float4* __restrict__ y0r = reinterpret_cast<const float4*>(
        scattered + ((((size_t)b * SS + 0) * AA + a) * (size_t)DD));
    const float4* __restrict__ y1r = reinterpret_cast<const float4*>(
        scattered + ((((size_t)b * SS + 1) * AA + a) * (size_t)DD));
    const float4* __restrict__ y2r = reinterpret_cast<const float4*>(
        scattered + ((((size_t)b * SS + 2) * AA + a) * (size_t)DD));

    const float4 x0  = __ldcs(&xr[lane]);
    const float4 x1  = __ldcs(&xr[lane + 32]);
    const float4 ya0 = __ldcs(&y0r[lane]);
    const float4 ya1 = __ldcs(&y0r[lane + 32]);
    const float4 yb0 = __ldcs(&y1r[lane]);
    const float4 yb1 = __ldcs(&y1r[lane + 32]);
    const float4 yc0 = __ldcs(&y2r[lane]);
    const float4 yc1 = __ldcs(&y2r[lane + 32]);

    // ---- Weights (512 floats = 128 float4): L1-resident after first wave ----
    const float4* __restrict__ wv = reinterpret_cast<const float4*>(weight);
    const float4 w1a = __ldg(&wv[lane]);
    const float4 w1b = __ldg(&wv[lane + 32]);
    const float4 w2a = __ldg(&wv[64 + lane]);
    const float4 w2b = __ldg(&wv[64 + lane + 32]);

    float p_in = x0.x * w1a.x + x0.y * w1a.y + x0.z * w1a.z + x0.w * w1a.w
               + x1.x * w1b.x + x1.y * w1b.y + x1.z * w1b.z + x1.w * w1b.w;
    float p0 = ya0.x * w2a.x + ya0.y * w2a.y + ya0.z * w2a.z + ya0.w * w2a.w
             + ya1.x * w2b.x + ya1.y * w2b.y + ya1.z * w2b.z + ya1.w * w2b.w;
    float p1 = yb0.x * w2a.x + yb0.y * w2a.y + yb0.z * w2a.z + yb0.w * w2a.w
             + yb1.x * w2b.x + yb1.y * w2b.y + yb1.z * w2b.z + yb1.w * w2b.w;
    float p2 = yc0.x * w2a.x + yc0.y * w2a.y + yc0.z * w2a.z + yc0.w * w2a.w
             + yc1.x * w2b.x + yc1.y * w2b.y + yc1.z * w2b.z + yc1.w * w2b.w;

    // Butterfly reduce all 4 partial dots.
#pragma unroll
    for (int off = 16; off > 0; off >>= 1) {
        p_in += __shfl_xor_sync(0xffffffffu, p_in, off);
        p0   += __shfl_xor_sync(0xffffffffu, p0, off);
        p1   += __shfl_xor_sync(0xffffffffu, p1, off);
        p2   += __shfl_xor_sync(0xffffffffu, p2, off);
    }

    const float alpha = __ldg(prelu);
    float sc0 = p_in + p0;
    float sc1 = p_in + p1;
    float sc2 = p_in + p2;
    sc0 = sc0 >= 0.f ? sc0 : alpha * sc0;
    sc1 = sc1 >= 0.f ? sc1 : alpha * sc1;
    sc2 = sc2 >= 0.f ? sc2 : alpha * sc2;

    const float m = fmaxf(sc0, fmaxf(sc1, sc2));
    const float e0 = __expf(sc0 - m);
    const float e1 = __expf(sc1 - m);
    const float e2 = __expf(sc2 - m);
    const float inv = 1.0f / (e0 + e1 + e2);

    if (lane < SS) {
        const float e = (lane == 0) ? e0 : (lane == 1 ? e1 : e2);
        __stcs(&out[((size_t)b * SS + lane) * AA + a], e * inv);
    }
}

extern "C" void kernel_launch(void* const* d_in, const int* in_sizes, int n_in,
                              void* d_out, int out_size)
{
    const float* input     = (const float*)d_in[0];  // (B, A, D) f32
    const float* scattered = (const float*)d_in[1];  // (B, S, A, D) f32
    const float* weight    = (const float*)d_in[2];  // (2D,) f32
    const float* prelu     = (const float*)d_in[3];  // (1,) f32
    float* out = (float*)d_out;                      // (B, S, A) f32

    const int total_warps = BB * AA;                 // 262144
    const int threads = 256;                         // 8 warps / block
    const int blocks = total_warps / (threads / 32); // 32768
    spectral_attention_kernel<<<blocks, threads>>>(input, scattered, weight, prelu, out);
}

// round 7
// speedup vs baseline: 1.0161x; 1.0088x over previous
#include <cuda_runtime.h>

// SpectralAttention: B=1024, S=3, A=256, D=256
// FINAL (= R2, best measured 148.8us): HBM-bound streaming reduction.
// 1.073 GB mandatory reads @ ~7.2 TB/s sustained = ~148.6us arithmetic floor;
// this kernel measures at that floor (DRAM ~91% of 8TB/s spec).
//
// Design: one warp per (b,a). All 8 stream LDG.128s (1 input row + 3 scattered
// rows, 2 vec-loads each) are front-batched with evict-first (.cs) policy;
// weights ride L1 (.ci). 4 CTAs/SM is the empirical optimum of the
// occupancy-vs-MLP curve (8/5 CTAs/SM and persistent/pipelined variants all
// measured slower). Butterfly-reduce 4 dots, PReLU, 3-way softmax in regs.

#define BB 1024
#define SS 3
#define AA 256
#define DD 256

__global__ __launch_bounds__(256, 4)
void spectral_attention_kernel(const float* __restrict__ input,
                               const float* __restrict__ scattered,
                               const float* __restrict__ weight,
                               const float* __restrict__ prelu,
                               float* __restrict__ out)
{
    const int lane = threadIdx.x & 31;
    const int warp = (blockIdx.x * blockDim.x + threadIdx.x) >> 5;  // 0 .. B*A-1
    const int b = warp >> 8;    // / AA
    const int a = warp & 255;   // % AA

    // ---- Front-batch ALL stream loads (8x LDG.128, evict-first) ----
    const float4* __restrict__ xr =
        reinterpret_cast<const float4*>(input + (((size_t)b * AA + a) * DD));
    const float4* __restrict__ y0r = reinterpret_cast<const float4*>(
        scattered + ((((size_t)b * SS + 0) * AA + a) * (size_t)DD));
    const float4* __restrict__ y1r = reinterpret_cast<const float4*>(
        scattered + ((((size_t)b * SS + 1) * AA + a) * (size_t)DD));
    const float4* __restrict__ y2r = reinterpret_cast<const float4*>(
        scattered + ((((size_t)b * SS + 2) * AA + a) * (size_t)DD));

    const float4 x0  = __ldcs(&xr[lane]);
    const float4 x1  = __ldcs(&xr[lane + 32]);
    const float4 ya0 = __ldcs(&y0r[lane]);
    const float4 ya1 = __ldcs(&y0r[lane + 32]);
    const float4 yb0 = __ldcs(&y1r[lane]);
    const float4 yb1 = __ldcs(&y1r[lane + 32]);
    const float4 yc0 = __ldcs(&y2r[lane]);
    const float4 yc1 = __ldcs(&y2r[lane + 32]);

    // ---- Weights (512 floats = 128 float4): L1-resident after first wave ----
    const float4* __restrict__ wv = reinterpret_cast<const float4*>(weight);
    const float4 w1a = __ldg(&wv[lane]);
    const float4 w1b = __ldg(&wv[lane + 32]);
    const float4 w2a = __ldg(&wv[64 + lane]);
    const float4 w2b = __ldg(&wv[64 + lane + 32]);

    float p_in = x0.x * w1a.x + x0.y * w1a.y + x0.z * w1a.z + x0.w * w1a.w
               + x1.x * w1b.x + x1.y * w1b.y + x1.z * w1b.z + x1.w * w1b.w;
    float p0 = ya0.x * w2a.x + ya0.y * w2a.y + ya0.z * w2a.z + ya0.w * w2a.w
             + ya1.x * w2b.x + ya1.y * w2b.y + ya1.z * w2b.z + ya1.w * w2b.w;
    float p1 = yb0.x * w2a.x + yb0.y * w2a.y + yb0.z * w2a.z + yb0.w * w2a.w
             + yb1.x * w2b.x + yb1.y * w2b.y + yb1.z * w2b.z + yb1.w * w2b.w;
    float p2 = yc0.x * w2a.x + yc0.y * w2a.y + yc0.z * w2a.z + yc0.w * w2a.w
             + yc1.x * w2b.x + yc1.y * w2b.y + yc1.z * w2b.z + yc1.w * w2b.w;

    // Butterfly reduce all 4 partial dots.
#pragma unroll
    for (int off = 16; off > 0; off >>= 1) {
        p_in += __shfl_xor_sync(0xffffffffu, p_in, off);
        p0   += __shfl_xor_sync(0xffffffffu, p0, off);
        p1   += __shfl_xor_sync(0xffffffffu, p1, off);
        p2   += __shfl_xor_sync(0xffffffffu, p2, off);
    }

    const float alpha = __ldg(prelu);
    float sc0 = p_in + p0;
    float sc1 = p_in + p1;
    float sc2 = p_in + p2;
    sc0 = sc0 >= 0.f ? sc0 : alpha * sc0;
    sc1 = sc1 >= 0.f ? sc1 : alpha * sc1;
    sc2 = sc2 >= 0.f ? sc2 : alpha * sc2;

    const float m = fmaxf(sc0, fmaxf(sc1, sc2));
    const float e0 = __expf(sc0 - m);
    const float e1 = __expf(sc1 - m);
    const float e2 = __expf(sc2 - m);
    const float inv = 1.0f / (e0 + e1 + e2);

    if (lane < SS) {
        const float e = (lane == 0) ? e0 : (lane == 1 ? e1 : e2);
        out[((size_t)b * SS + lane) * AA + a] = e * inv;
    }
}

extern "C" void kernel_launch(void* const* d_in, const int* in_sizes, int n_in,
                              void* d_out, int out_size)
{
    const float* input     = (const float*)d_in[0];  // (B, A, D) f32
    const float* scattered = (const float*)d_in[1];  // (B, S, A, D) f32
    const float* weight    = (const float*)d_in[2];  // (2D,) f32
    const float* prelu     = (const float*)d_in[3];  // (1,) f32
    float* out = (float*)d_out;                      // (B, S, A) f32

    const int total_warps = BB * AA;                 // 262144
    const int threads = 256;                         // 8 warps / block
    const int blocks = total_warps / (threads / 32); // 32768
    spectral_attention_kernel<<<blocks, threads>>>(input, scattered, weight, prelu, out);
}